// round 1
// baseline (speedup 1.0000x reference)
#include <cuda_runtime.h>
#include <math.h>

// Problem constants
#define BB   8
#define HW   14400   // 120*120
#define WATT 120
#define NP   10
#define PH   100
#define PW   100
#define CC   3
#define HH   1024
#define WHI  1024

// d_out layout (flattened return tuple, all f32):
//   [0, 2400000)            patches (B,N,100,100,3)
//   [2400000, 2400080)      sampled_attention (B,N)
//   [2400080, 2400240)      offsets (B,N,2)
//   [2400240, 2400400)      samples (B,N,2) as float
#define PATCH_ELEMS (BB*NP*PH*PW*CC)   // 2,400,000

// Scratch (no cudaMalloc allowed)
__device__ float g_scores[BB * HW];
__device__ int   g_corners[BB * NP * 2];

// ---------------------------------------------------------------------------
// Kernel 1: per-batch Gumbel scores + iterative top-10 argmax
// grid = B, block = 1024
// ---------------------------------------------------------------------------
__global__ void topk_kernel(const float* __restrict__ att,
                            const float* __restrict__ u,
                            float* __restrict__ out)
{
    const int b   = blockIdx.x;
    const int tid = threadIdx.x;
    const int nt  = blockDim.x;

    float* sc = g_scores + b * HW;
    const float* a  = att + b * HW;
    const float* uu = u   + b * HW;

    // 1. compute scores: log(max(att,1e-20)) - log(-log(clip(u,1e-6,1-1e-6)))
    for (int i = tid; i < HW; i += nt) {
        float av = a[i];
        float uv = fminf(fmaxf(uu[i], 1e-6f), 1.0f - 1e-6f);
        sc[i] = logf(fmaxf(av, 1e-20f)) - logf(-logf(uv));
    }

    __shared__ float sv[1024];
    __shared__ int   si[1024];

    float* o_att  = out + PATCH_ELEMS;          // (B,N)
    float* o_off  = o_att + BB * NP;            // (B,N,2)
    float* o_samp = o_off + BB * NP * 2;        // (B,N,2)

    for (int k = 0; k < NP; k++) {
        __syncthreads();  // scores (and previous -inf poke) visible block-wide

        // strided scan: strict > keeps the earliest (lowest) index on ties
        float bv = -INFINITY; int bi = HW;
        for (int i = tid; i < HW; i += nt) {
            float v = sc[i];
            if (v > bv) { bv = v; bi = i; }
        }
        sv[tid] = bv; si[tid] = bi;
        __syncthreads();

        // tree reduce; ties -> lower index (matches jax.lax.top_k)
        for (int s = nt >> 1; s > 0; s >>= 1) {
            if (tid < s) {
                float v2 = sv[tid + s]; int i2 = si[tid + s];
                if (v2 > sv[tid] || (v2 == sv[tid] && i2 < si[tid])) {
                    sv[tid] = v2; si[tid] = i2;
                }
            }
            __syncthreads();
        }

        if (tid == 0) {
            int wi = si[0];
            sc[wi] = -INFINITY;                 // remove winner for next pass

            int iy = wi / WATT;
            int ix = wi % WATT;

            o_att[b * NP + k] = a[wi];
            // offsets = (sample + RF/2) * scale = (s+4)*8 (exact ints)
            o_off[(b * NP + k) * 2 + 0] = (float)((iy + 4) * 8);
            o_off[(b * NP + k) * 2 + 1] = (float)((ix + 4) * 8);
            o_samp[(b * NP + k) * 2 + 0] = (float)iy;
            o_samp[(b * NP + k) * 2 + 1] = (float)ix;

            // dynamic_slice clamp: start <= H-ph (=924); lower bound always >=32
            int cy = (iy + 4) * 8; if (cy > HH  - PH) cy = HH  - PH;
            int cx = (ix + 4) * 8; if (cx > WHI - PW) cx = WHI - PW;
            g_corners[(b * NP + k) * 2 + 0] = cy;
            g_corners[(b * NP + k) * 2 + 1] = cx;
        }
    }
}

// ---------------------------------------------------------------------------
// Kernel 2: patch gather, one thread per output element (coalesced)
// ---------------------------------------------------------------------------
__global__ void gather_kernel(const float* __restrict__ xh,
                              float* __restrict__ out)
{
    int t = blockIdx.x * blockDim.x + threadIdx.x;
    if (t >= PATCH_ELEMS) return;

    int c  = t % CC;
    int x  = (t / CC) % PW;
    int y  = (t / (CC * PW)) % PH;
    int n  = (t / (CC * PW * PH)) % NP;
    int b  = t / (CC * PW * PH * NP);

    int cy = g_corners[(b * NP + n) * 2 + 0];
    int cx = g_corners[(b * NP + n) * 2 + 1];

    out[t] = xh[((b * HH + cy + y) * WHI + cx + x) * CC + c];
}

// ---------------------------------------------------------------------------
extern "C" void kernel_launch(void* const* d_in, const int* in_sizes, int n_in,
                              void* d_out, int out_size)
{
    // metadata order: x_low, x_high, attention, uniform_noise
    const float* x_high = (const float*)d_in[1];
    const float* att    = (const float*)d_in[2];
    const float* unoise = (const float*)d_in[3];
    float* out = (float*)d_out;

    topk_kernel<<<BB, 1024>>>(att, unoise, out);

    const int threads = 256;
    const int blocks  = (PATCH_ELEMS + threads - 1) / threads;
    gather_kernel<<<blocks, threads>>>(x_high, out);
}

// round 2
// speedup vs baseline: 1.9000x; 1.9000x over previous
#include <cuda_runtime.h>
#include <math.h>

// Problem constants
#define BB   8
#define HW   14400   // 120*120
#define HWP  15360   // padded to 15*1024
#define WATT 120
#define NP   10
#define PH   100
#define PW   100
#define CC   3
#define HH   1024
#define WHI  1024

// d_out layout (flattened return tuple, all f32):
//   [0, 2400000)            patches (B,N,100,100,3)
//   [2400000, 2400080)      sampled_attention (B,N)
//   [2400080, 2400240)      offsets (B,N,2)
//   [2400240, 2400400)      samples (B,N,2) as float
#define PATCH_ELEMS (BB*NP*PH*PW*CC)   // 2,400,000
#define ROW_VEC     75                 // 300 floats per patch row = 75 float4
#define TOTAL_VEC   (PATCH_ELEMS/4)    // 600,000

__device__ int g_corners[BB * NP * 2];

// ---------------------------------------------------------------------------
// Kernel 1: per-batch Gumbel scores in SMEM + 10x argmax via warp shuffles
// grid = B, block = 1024, dynamic smem = HWP floats + reduce scratch
// ---------------------------------------------------------------------------
__global__ void topk_kernel(const float* __restrict__ att,
                            const float* __restrict__ u,
                            float* __restrict__ out)
{
    extern __shared__ float ssc[];                  // [HWP]
    __shared__ float swv[32];
    __shared__ int   swi[32];

    const int b    = blockIdx.x;
    const int tid  = threadIdx.x;
    const int lane = tid & 31;
    const int warp = tid >> 5;

    const float* a  = att + b * HW;
    const float* uu = u   + b * HW;

    // scores: log(max(att,1e-20)) - log(-log(clip(u,1e-6,1-1e-6)))
    #pragma unroll
    for (int j = 0; j < 15; j++) {
        int i = tid + j * 1024;
        if (i < HW) {
            float uv = fminf(fmaxf(uu[i], 1e-6f), 1.0f - 1e-6f);
            ssc[i] = logf(fmaxf(a[i], 1e-20f)) - logf(-logf(uv));
        } else {
            ssc[i] = -INFINITY;                     // pad region
        }
    }

    float* o_att  = out + PATCH_ELEMS;              // (B,N)
    float* o_off  = o_att + BB * NP;                // (B,N,2)
    float* o_samp = o_off + BB * NP * 2;            // (B,N,2)

    for (int k = 0; k < NP; k++) {
        __syncthreads();                            // scores / poison visible

        // branch-free strided scan over padded smem; strict > keeps lowest idx
        float bv = -INFINITY; int bi = HWP;
        #pragma unroll
        for (int j = 0; j < 15; j++) {
            int i = tid + j * 1024;
            float v = ssc[i];
            if (v > bv) { bv = v; bi = i; }
        }

        // warp shuffle reduce, ties -> lower index
        #pragma unroll
        for (int s = 16; s > 0; s >>= 1) {
            float ov = __shfl_down_sync(0xffffffffu, bv, s);
            int   oi = __shfl_down_sync(0xffffffffu, bi, s);
            if (ov > bv || (ov == bv && oi < bi)) { bv = ov; bi = oi; }
        }
        if (lane == 0) { swv[warp] = bv; swi[warp] = bi; }
        __syncthreads();

        if (warp == 0) {
            bv = swv[lane]; bi = swi[lane];
            #pragma unroll
            for (int s = 16; s > 0; s >>= 1) {
                float ov = __shfl_down_sync(0xffffffffu, bv, s);
                int   oi = __shfl_down_sync(0xffffffffu, bi, s);
                if (ov > bv || (ov == bv && oi < bi)) { bv = ov; bi = oi; }
            }
            if (lane == 0) {
                int wi = bi;
                ssc[wi] = -INFINITY;                // remove winner

                int iy = wi / WATT;
                int ix = wi % WATT;

                o_att[b * NP + k] = a[wi];
                // offsets = (sample + RF/2) * scale = (s+4)*8 exactly
                o_off[(b * NP + k) * 2 + 0] = (float)((iy + 4) * 8);
                o_off[(b * NP + k) * 2 + 1] = (float)((ix + 4) * 8);
                o_samp[(b * NP + k) * 2 + 0] = (float)iy;
                o_samp[(b * NP + k) * 2 + 1] = (float)ix;

                // dynamic_slice clamp (upper only; lower bound is >= 32)
                int cy = (iy + 4) * 8; if (cy > HH  - PH) cy = HH  - PH;
                int cx = (ix + 4) * 8; if (cx > WHI - PW) cx = WHI - PW;
                g_corners[(b * NP + k) * 2 + 0] = cy;
                g_corners[(b * NP + k) * 2 + 1] = cx;
            }
        }
    }
}

// ---------------------------------------------------------------------------
// Kernel 2: patch gather, one float4 per thread (rows are 16B aligned:
// cx is a multiple of 4 so cx*3 % 4 == 0; 300 floats/out-row % 4 == 0)
// ---------------------------------------------------------------------------
__global__ void gather_kernel(const float* __restrict__ xh,
                              float* __restrict__ out)
{
    int v = blockIdx.x * blockDim.x + threadIdx.x;
    if (v >= TOTAL_VEC) return;

    int col = v % ROW_VEC;           // which float4 within the 300-float row
    int row = v / ROW_VEC;           // global patch-row id = (b*NP+n)*PH + y
    int y   = row % PH;
    int pn  = row / PH;              // b*NP + n

    int cy = g_corners[pn * 2 + 0];
    int cx = g_corners[pn * 2 + 1];
    int b  = pn / NP;

    const float4* src = reinterpret_cast<const float4*>(
        xh + ((size_t)(b * HH + cy + y) * WHI + cx) * CC);
    reinterpret_cast<float4*>(out)[v] = src[col];
}

// ---------------------------------------------------------------------------
extern "C" void kernel_launch(void* const* d_in, const int* in_sizes, int n_in,
                              void* d_out, int out_size)
{
    // metadata order: x_low, x_high, attention, uniform_noise
    const float* x_high = (const float*)d_in[1];
    const float* att    = (const float*)d_in[2];
    const float* unoise = (const float*)d_in[3];
    float* out = (float*)d_out;

    static bool attr_set = false;
    if (!attr_set) {
        cudaFuncSetAttribute(topk_kernel,
                             cudaFuncAttributeMaxDynamicSharedMemorySize,
                             HWP * (int)sizeof(float));
        attr_set = true;
    }

    topk_kernel<<<BB, 1024, HWP * sizeof(float)>>>(att, unoise, out);

    const int threads = 256;
    const int blocks  = (TOTAL_VEC + threads - 1) / threads;
    gather_kernel<<<blocks, threads>>>(x_high, out);
}

// round 3
// speedup vs baseline: 2.0885x; 1.0992x over previous
#include <cuda_runtime.h>
#include <math.h>

// Problem constants
#define BB   8
#define HW   14400   // 120*120
#define WATT 120
#define NP   10
#define PH   100
#define PW   100
#define CC   3
#define HH   1024
#define WHI  1024

#define CH    30     // chunks per batch
#define CHUNK 480    // elements per chunk (32 lanes x 15)
#define NC    (CH*NP)  // 300 candidates per batch

// d_out layout (flattened return tuple, all f32):
//   [0, 2400000)            patches (B,N,100,100,3)
//   [2400000, 2400080)      sampled_attention (B,N)
//   [2400080, 2400240)      offsets (B,N,2)
//   [2400240, 2400400)      samples (B,N,2) as float
#define PATCH_ELEMS (BB*NP*PH*PW*CC)   // 2,400,000
#define ROW_VEC     75                 // 300 floats per patch row = 75 float4
#define TOTAL_VEC   (PATCH_ELEMS/4)    // 600,000
#define GSTRIDE     (TOTAL_VEC/4)      // 150,000 (unroll factor 4)

__device__ int   g_corners[BB * NP * 2];
__device__ float g_cval[BB * NC];
__device__ int   g_cidx[BB * NC];

// ---------------------------------------------------------------------------
// Kernel A: per-warp chunk scores (registers) + local top-10 via shuffles.
// No barriers, no smem. 240 warps total.
// ---------------------------------------------------------------------------
__global__ void score_topk_kernel(const float* __restrict__ att,
                                  const float* __restrict__ u)
{
    const int wg   = (blockIdx.x * blockDim.x + threadIdx.x) >> 5; // global warp
    const int lane = threadIdx.x & 31;
    if (wg >= BB * CH) return;   // warp-uniform

    const int b    = wg / CH;
    const int ch   = wg % CH;
    const int base = ch * CHUNK;

    const float* a  = att + b * HW;
    const float* uu = u   + b * HW;

    // scores: log(max(att,1e-20)) - log(-log(clip(u,1e-6,1-1e-6)))
    float vals[15];
    #pragma unroll
    for (int j = 0; j < 15; j++) {
        int i = base + j * 32 + lane;
        float uv = fminf(fmaxf(uu[i], 1e-6f), 1.0f - 1e-6f);
        vals[j] = logf(fmaxf(a[i], 1e-20f)) - logf(-logf(uv));
    }

    for (int k = 0; k < NP; k++) {
        // per-lane argmax over 15 regs (strict > keeps lowest slot j -> lowest idx)
        float bv = -INFINITY; int bj = 0;
        #pragma unroll
        for (int j = 0; j < 15; j++)
            if (vals[j] > bv) { bv = vals[j]; bj = j; }
        int gidx = base + bj * 32 + lane;

        // warp reduce, ties -> lower global index
        #pragma unroll
        for (int s = 16; s > 0; s >>= 1) {
            float ov = __shfl_down_sync(0xffffffffu, bv, s);
            int   oi = __shfl_down_sync(0xffffffffu, gidx, s);
            if (ov > bv || (ov == bv && oi < gidx)) { bv = ov; gidx = oi; }
        }
        bv   = __shfl_sync(0xffffffffu, bv, 0);
        gidx = __shfl_sync(0xffffffffu, gidx, 0);

        if (lane == 0) {
            g_cval[(b * CH + ch) * NP + k] = bv;
            g_cidx[(b * CH + ch) * NP + k] = gidx;
        }

        // poison winner: only the lane/slot matching gidx
        int rel = gidx - base;
        if (lane == (rel & 31)) {
            int ws = rel >> 5;
            #pragma unroll
            for (int j = 0; j < 15; j++)
                if (j == ws) vals[j] = -INFINITY;
        }
    }
}

// ---------------------------------------------------------------------------
// Kernel B: merge 300 candidates per batch -> global top-10. grid=B, 1 warp.
// ---------------------------------------------------------------------------
__global__ void merge_topk_kernel(const float* __restrict__ att,
                                  float* __restrict__ out)
{
    const int b    = blockIdx.x;
    const int lane = threadIdx.x;

    float vals[10]; int idxs[10];
    #pragma unroll
    for (int j = 0; j < 10; j++) {
        int c = j * 32 + lane;
        if (c < NC) { vals[j] = g_cval[b * NC + c]; idxs[j] = g_cidx[b * NC + c]; }
        else        { vals[j] = -INFINITY;          idxs[j] = 0x7fffffff; }
    }

    float* o_att  = out + PATCH_ELEMS;
    float* o_off  = o_att + BB * NP;
    float* o_samp = o_off + BB * NP * 2;

    for (int k = 0; k < NP; k++) {
        float bv = -INFINITY; int bi = 0x7fffffff;
        #pragma unroll
        for (int j = 0; j < 10; j++)
            if (vals[j] > bv || (vals[j] == bv && idxs[j] < bi)) { bv = vals[j]; bi = idxs[j]; }

        #pragma unroll
        for (int s = 16; s > 0; s >>= 1) {
            float ov = __shfl_down_sync(0xffffffffu, bv, s);
            int   oi = __shfl_down_sync(0xffffffffu, bi, s);
            if (ov > bv || (ov == bv && oi < bi)) { bv = ov; bi = oi; }
        }
        bi = __shfl_sync(0xffffffffu, bi, 0);

        if (lane == 0) {
            int wi = bi;
            int iy = wi / WATT;
            int ix = wi % WATT;

            o_att[b * NP + k] = att[b * HW + wi];
            // offsets = (sample + RF/2) * scale = (s+4)*8 exactly
            o_off[(b * NP + k) * 2 + 0] = (float)((iy + 4) * 8);
            o_off[(b * NP + k) * 2 + 1] = (float)((ix + 4) * 8);
            o_samp[(b * NP + k) * 2 + 0] = (float)iy;
            o_samp[(b * NP + k) * 2 + 1] = (float)ix;

            int cy = (iy + 4) * 8; if (cy > HH  - PH) cy = HH  - PH;
            int cx = (ix + 4) * 8; if (cx > WHI - PW) cx = WHI - PW;
            g_corners[(b * NP + k) * 2 + 0] = cy;
            g_corners[(b * NP + k) * 2 + 1] = cx;
        }

        // poison the winner (unique global index -> exactly one slot matches)
        #pragma unroll
        for (int j = 0; j < 10; j++)
            if (idxs[j] == bi) vals[j] = -INFINITY;
    }
}

// ---------------------------------------------------------------------------
// Kernel C: patch gather, 4 independent float4s per thread (MLP=4)
// ---------------------------------------------------------------------------
__global__ void gather_kernel(const float* __restrict__ xh,
                              float* __restrict__ out)
{
    int t = blockIdx.x * blockDim.x + threadIdx.x;
    if (t >= GSTRIDE) return;

    #pragma unroll
    for (int r = 0; r < 4; r++) {
        int v = t + r * GSTRIDE;

        int col = v % ROW_VEC;
        int row = v / ROW_VEC;
        int y   = row % PH;
        int pn  = row / PH;              // b*NP + n

        int cy = g_corners[pn * 2 + 0];
        int cx = g_corners[pn * 2 + 1];
        int b  = pn / NP;

        const float4* src = reinterpret_cast<const float4*>(
            xh + ((size_t)(b * HH + cy + y) * WHI + cx) * CC);
        reinterpret_cast<float4*>(out)[v] = src[col];
    }
}

// ---------------------------------------------------------------------------
extern "C" void kernel_launch(void* const* d_in, const int* in_sizes, int n_in,
                              void* d_out, int out_size)
{
    // metadata order: x_low, x_high, attention, uniform_noise
    const float* x_high = (const float*)d_in[1];
    const float* att    = (const float*)d_in[2];
    const float* unoise = (const float*)d_in[3];
    float* out = (float*)d_out;

    // Kernel A: 240 warps, 2 warps/block -> 120 blocks
    score_topk_kernel<<<120, 64>>>(att, unoise);
    // Kernel B: one warp per batch
    merge_topk_kernel<<<BB, 32>>>(att, out);
    // Kernel C: gather
    const int threads = 256;
    const int blocks  = (GSTRIDE + threads - 1) / threads;
    gather_kernel<<<blocks, threads>>>(x_high, out);
}

// round 4
// speedup vs baseline: 2.5570x; 1.2243x over previous
#include <cuda_runtime.h>
#include <math.h>

// Problem constants
#define BB   8
#define HW   14400   // 120*120
#define WATT 120
#define NP   10
#define PH   100
#define PW   100
#define CC   3
#define HH   1024
#define WHI  1024

#define CH    30       // chunks per batch
#define CHUNK 480      // elements per chunk (32 lanes x 15)
#define NC    (CH*NP)  // 300 candidates per batch

// d_out layout (flattened return tuple, all f32):
//   [0, 2400000)            patches (B,N,100,100,3)
//   [2400000, 2400080)      sampled_attention (B,N)
//   [2400080, 2400240)      offsets (B,N,2)
//   [2400240, 2400400)      samples (B,N,2) as float
#define PATCH_ELEMS (BB*NP*PH*PW*CC)   // 2,400,000
#define ROW_VEC     75                 // 300 floats per patch row = 75 float4
#define TOTAL_VEC   (PATCH_ELEMS/4)    // 600,000
#define GSTRIDE     (TOTAL_VEC/4)      // 150,000 (unroll factor 4)

#define FULL 0xffffffffu

__device__ int   g_corners[BB * NP * 2];
__device__ float g_cval[BB * NC];
__device__ int   g_cidx[BB * NC];

// ---------------------------------------------------------------------------
// Kernel A: per-warp chunk scores (registers) + top-10 via value-only
// butterfly max + equality-based index recovery. No smem, no index in chain.
// ---------------------------------------------------------------------------
__global__ void __launch_bounds__(128, 1)
score_topk_kernel(const float* __restrict__ att,
                  const float* __restrict__ u)
{
    const int wg   = (blockIdx.x * blockDim.x + threadIdx.x) >> 5;
    const int lane = threadIdx.x & 31;
    if (wg >= BB * CH) return;   // warp-uniform

    const int b    = wg / CH;
    const int ch   = wg % CH;
    const int base = ch * CHUNK;

    const float* a  = att + b * HW;
    const float* uu = u   + b * HW;

    // scores: log(max(att,1e-20)) - log(-log(clip(u,1e-6,1-1e-6)))
    float lv[16];
    #pragma unroll
    for (int j = 0; j < 15; j++) {
        int i = base + j * 32 + lane;
        float uv = fminf(fmaxf(uu[i], 1e-6f), 1.0f - 1e-6f);
        lv[j] = logf(fmaxf(a[i], 1e-20f)) - logf(-logf(uv));
    }
    lv[15] = -INFINITY;

    #pragma unroll 1
    for (int k = 0; k < NP; k++) {
        // lane max: pairwise fmaxf tree, depth 4, no index tracking
        float t8[8], t4[4], t2[2];
        #pragma unroll
        for (int j = 0; j < 8; j++) t8[j] = fmaxf(lv[2*j], lv[2*j+1]);
        #pragma unroll
        for (int j = 0; j < 4; j++) t4[j] = fmaxf(t8[2*j], t8[2*j+1]);
        t2[0] = fmaxf(t4[0], t4[1]);
        t2[1] = fmaxf(t4[2], t4[3]);
        float wmax = fmaxf(t2[0], t2[1]);

        // warp max: 5 butterfly steps, value only, all lanes get result
        #pragma unroll
        for (int s = 16; s > 0; s >>= 1)
            wmax = fmaxf(wmax, __shfl_xor_sync(FULL, wmax, s));

        // recover owner lane + slot by equality (ties measure-zero)
        unsigned bits = 0;
        #pragma unroll
        for (int j = 0; j < 15; j++)
            if (lv[j] == wmax) bits |= (1u << j);
        unsigned m = __ballot_sync(FULL, bits != 0);
        int owner = __ffs(m) - 1;
        int slot  = __ffs(bits) - 1;              // valid on owner
        slot = __shfl_sync(FULL, slot, owner);

        if (lane == 0) {
            g_cval[(b * CH + ch) * NP + k] = wmax;
            g_cidx[(b * CH + ch) * NP + k] = base + slot * 32 + owner;
        }

        // poison winner (constant-index predicated writes)
        bool own = (lane == owner);
        #pragma unroll
        for (int j = 0; j < 15; j++)
            if (own && j == slot) lv[j] = -INFINITY;
    }
}

// ---------------------------------------------------------------------------
// Kernel B: merge 300 candidates per batch -> global top-10. grid=B, 1 warp.
// Same value-only machinery.
// ---------------------------------------------------------------------------
__global__ void __launch_bounds__(32, 1)
merge_topk_kernel(const float* __restrict__ att,
                  float* __restrict__ out)
{
    const int b    = blockIdx.x;
    const int lane = threadIdx.x;

    float cv[10]; int ci[10];
    #pragma unroll
    for (int j = 0; j < 10; j++) {
        int c = j * 32 + lane;
        if (c < NC) { cv[j] = g_cval[b * NC + c]; ci[j] = g_cidx[b * NC + c]; }
        else        { cv[j] = -INFINITY;          ci[j] = 0; }
    }

    float* o_att  = out + PATCH_ELEMS;
    float* o_off  = o_att + BB * NP;
    float* o_samp = o_off + BB * NP * 2;

    #pragma unroll 1
    for (int k = 0; k < NP; k++) {
        // lane max tree over 10 (pad to 16 behavior via pairs)
        float p0 = fmaxf(cv[0], cv[1]);
        float p1 = fmaxf(cv[2], cv[3]);
        float p2 = fmaxf(cv[4], cv[5]);
        float p3 = fmaxf(cv[6], cv[7]);
        float p4 = fmaxf(cv[8], cv[9]);
        float q0 = fmaxf(p0, p1);
        float q1 = fmaxf(p2, p3);
        float wmax = fmaxf(fmaxf(q0, q1), p4);

        #pragma unroll
        for (int s = 16; s > 0; s >>= 1)
            wmax = fmaxf(wmax, __shfl_xor_sync(FULL, wmax, s));

        unsigned bits = 0;
        #pragma unroll
        for (int j = 0; j < 10; j++)
            if (cv[j] == wmax) bits |= (1u << j);
        unsigned m = __ballot_sync(FULL, bits != 0);
        int owner = __ffs(m) - 1;
        int slot  = __ffs(bits) - 1;

        // owner extracts its candidate's global index, broadcast it
        int gi = 0;
        #pragma unroll
        for (int j = 0; j < 10; j++)
            if (j == slot) gi = ci[j];
        gi = __shfl_sync(FULL, gi, owner);

        if (lane == 0) {
            int wi = gi;
            int iy = wi / WATT;
            int ix = wi % WATT;

            o_att[b * NP + k] = att[b * HW + wi];
            // offsets = (sample + RF/2) * scale = (s+4)*8 exactly
            o_off[(b * NP + k) * 2 + 0] = (float)((iy + 4) * 8);
            o_off[(b * NP + k) * 2 + 1] = (float)((ix + 4) * 8);
            o_samp[(b * NP + k) * 2 + 0] = (float)iy;
            o_samp[(b * NP + k) * 2 + 1] = (float)ix;

            int cy = (iy + 4) * 8; if (cy > HH  - PH) cy = HH  - PH;
            int cx = (ix + 4) * 8; if (cx > WHI - PW) cx = WHI - PW;
            g_corners[(b * NP + k) * 2 + 0] = cy;
            g_corners[(b * NP + k) * 2 + 1] = cx;
        }

        // poison
        bool own = (lane == owner);
        slot = __shfl_sync(FULL, slot, owner);   // ensure defined on all lanes
        #pragma unroll
        for (int j = 0; j < 10; j++)
            if (own && j == slot) cv[j] = -INFINITY;
    }
}

// ---------------------------------------------------------------------------
// Kernel C: patch gather, 4 independent float4s per thread (MLP=4)
// ---------------------------------------------------------------------------
__global__ void __launch_bounds__(256)
gather_kernel(const float* __restrict__ xh,
              float* __restrict__ out)
{
    int t = blockIdx.x * blockDim.x + threadIdx.x;
    if (t >= GSTRIDE) return;

    #pragma unroll
    for (int r = 0; r < 4; r++) {
        int v = t + r * GSTRIDE;

        int col = v % ROW_VEC;
        int row = v / ROW_VEC;
        int y   = row % PH;
        int pn  = row / PH;              // b*NP + n

        int cy = g_corners[pn * 2 + 0];
        int cx = g_corners[pn * 2 + 1];
        int b  = pn / NP;

        const float4* src = reinterpret_cast<const float4*>(
            xh + ((size_t)(b * HH + cy + y) * WHI + cx) * CC);
        reinterpret_cast<float4*>(out)[v] = src[col];
    }
}

// ---------------------------------------------------------------------------
extern "C" void kernel_launch(void* const* d_in, const int* in_sizes, int n_in,
                              void* d_out, int out_size)
{
    // metadata order: x_low, x_high, attention, uniform_noise
    const float* x_high = (const float*)d_in[1];
    const float* att    = (const float*)d_in[2];
    const float* unoise = (const float*)d_in[3];
    float* out = (float*)d_out;

    // Kernel A: 240 warps, 4 warps/block -> 60 blocks
    score_topk_kernel<<<60, 128>>>(att, unoise);
    // Kernel B: one warp per batch
    merge_topk_kernel<<<BB, 32>>>(att, out);
    // Kernel C: gather
    const int threads = 256;
    const int blocks  = (GSTRIDE + threads - 1) / threads;
    gather_kernel<<<blocks, threads>>>(x_high, out);
}